// round 3
// baseline (speedup 1.0000x reference)
#include <cuda_runtime.h>
#include <cuda_bf16.h>

#define IN_C 128
#define MAX_NODES 10000
#define MAX_EDGES 640000

// Scratch (allocation-free rule: __device__ globals)
__device__ float g_h[MAX_NODES * IN_C];       // x @ W^T
__device__ float g_Wt[IN_C * IN_C];           // W transposed: Wt[k][o] = W[o][k]
__device__ int   g_deg[MAX_NODES];
__device__ float g_dinv[MAX_NODES];
__device__ int   g_row[MAX_EDGES];
__device__ int   g_col[MAX_EDGES];
__device__ int   g_is64;

// ---------------------------------------------------------------------------
// Edge-index dtype detection: if stored as int64 (values < 2^31, >= 0),
// every odd 32-bit word of the first 256 pairs is zero. If int32, those words
// are uniform random node ids — essentially never all zero.
// ---------------------------------------------------------------------------
__global__ void k_detect(const int* __restrict__ ei32) {
    __shared__ int nz;
    if (threadIdx.x == 0) nz = 0;
    __syncthreads();
    if (ei32[2 * threadIdx.x + 1] != 0) atomicAdd(&nz, 1);
    __syncthreads();
    if (threadIdx.x == 0) g_is64 = (nz == 0) ? 1 : 0;
}

// Convert edge index (either dtype) to int32 row/col arrays.
__global__ void k_convert(const void* __restrict__ ei_raw, int E) {
    int e = blockIdx.x * blockDim.x + threadIdx.x;
    if (e >= E) return;
    if (g_is64) {
        const long long* p = (const long long*)ei_raw;
        g_row[e] = (int)p[e];
        g_col[e] = (int)p[(size_t)E + e];
    } else {
        const int* p = (const int*)ei_raw;
        g_row[e] = p[e];
        g_col[e] = p[E + e];
    }
}

// ---------------------------------------------------------------------------
// W transpose: Wt[k*128 + o] = W[o*128 + k]
// ---------------------------------------------------------------------------
__global__ void k_transpose(const float* __restrict__ W) {
    int idx = blockIdx.x * blockDim.x + threadIdx.x;   // 16384 threads
    int o = idx >> 7;          // / IN_C
    int k = idx & (IN_C - 1);  // % IN_C
    g_Wt[k * IN_C + o] = W[o * IN_C + k];
}

// ---------------------------------------------------------------------------
// Degree (includes the self loop: init to 1), then dinv = rsqrt(deg)
// ---------------------------------------------------------------------------
__global__ void k_deg_init(int n) {
    int i = blockIdx.x * blockDim.x + threadIdx.x;
    if (i < n) g_deg[i] = 1;
}

__global__ void k_deg_count(int E) {
    int e = blockIdx.x * blockDim.x + threadIdx.x;
    if (e < E) atomicAdd(&g_deg[g_col[e]], 1);
}

__global__ void k_dinv(int n) {
    int i = blockIdx.x * blockDim.x + threadIdx.x;
    if (i < n) g_dinv[i] = rsqrtf((float)g_deg[i]);
}

// ---------------------------------------------------------------------------
// GEMM: g_h = x @ W^T. Block = 256 threads, 32 rows x 128 cols.
// 8 warps: 2 row-groups (16 rows) x 4 col-groups (32 cols).
// x tile staged in shared (broadcast reads), Wt read via LDG (L1-resident 64KB).
// ---------------------------------------------------------------------------
#define GM_ROWS 32
__global__ void k_gemm(const float* __restrict__ x, int n) {
    __shared__ float xs[GM_ROWS][IN_C];

    int rowbase = blockIdx.x * GM_ROWS;
    int tid = threadIdx.x;
    int nrows = n - rowbase; if (nrows > GM_ROWS) nrows = GM_ROWS;

    // Load xs: 32*128 floats = 1024 float4s, 256 threads x 4
    const float4* xg = (const float4*)(x + (size_t)rowbase * IN_C);
    float4* xs4 = (float4*)&xs[0][0];
#pragma unroll
    for (int i = 0; i < 4; i++) {
        int idx = tid + i * 256;          // float4 index; 32 float4 per row
        if ((idx >> 5) < nrows) xs4[idx] = xg[idx];
    }
    __syncthreads();

    int warp = tid >> 5, lane = tid & 31;
    int rg = warp >> 2;                       // row group (0..1)
    int o  = ((warp & 3) << 5) + lane;        // output column (0..127)

    float acc[16];
#pragma unroll
    for (int r = 0; r < 16; r++) acc[r] = 0.0f;

    const float* xbase = &xs[rg * 16][0];

#pragma unroll 4
    for (int k = 0; k < IN_C; k++) {
        float w = __ldg(&g_Wt[k * IN_C + o]);
#pragma unroll
        for (int r = 0; r < 16; r++)
            acc[r] += xbase[r * IN_C + k] * w;
    }

    int rmax = nrows - rg * 16;
#pragma unroll
    for (int r = 0; r < 16; r++) {
        if (r < rmax)
            g_h[(size_t)(rowbase + rg * 16 + r) * IN_C + o] = acc[r];
    }
}

// ---------------------------------------------------------------------------
// Init output with the self-loop term + bias: out[i] = dinv[i]^2 * h[i] + b
// One float4 per thread.
// ---------------------------------------------------------------------------
__global__ void k_selfinit(const float* __restrict__ b, float* __restrict__ out, int n) {
    int idx = blockIdx.x * blockDim.x + threadIdx.x;  // n*32 float4 slots
    int i = idx >> 5;
    if (i >= n) return;
    int c4 = idx & 31;
    float d = g_dinv[i];
    float s = d * d;
    float4 h = *(const float4*)(g_h + (size_t)i * IN_C + c4 * 4);
    float4 bb = *(const float4*)(b + c4 * 4);
    float4 o;
    o.x = fmaf(h.x, s, bb.x);
    o.y = fmaf(h.y, s, bb.y);
    o.z = fmaf(h.z, s, bb.z);
    o.w = fmaf(h.w, s, bb.w);
    *(float4*)(out + (size_t)i * IN_C + c4 * 4) = o;
}

// ---------------------------------------------------------------------------
// Edge scatter: warp per edge, lane handles 4 channels.
// out[col] += dinv[row]*dinv[col] * h[row], scalar fp32 REDs (no-return).
// ---------------------------------------------------------------------------
__global__ void k_scatter(float* __restrict__ out, int E) {
    int wid = (blockIdx.x * blockDim.x + threadIdx.x) >> 5;
    if (wid >= E) return;
    int lane = threadIdx.x & 31;
    int row = g_row[wid];
    int col = g_col[wid];
    float norm = g_dinv[row] * g_dinv[col];

    float4 v = *(const float4*)(g_h + (size_t)row * IN_C + lane * 4);

    float* dst = out + (size_t)col * IN_C + lane * 4;
    atomicAdd(dst + 0, v.x * norm);
    atomicAdd(dst + 1, v.y * norm);
    atomicAdd(dst + 2, v.z * norm);
    atomicAdd(dst + 3, v.w * norm);
}

// ---------------------------------------------------------------------------
extern "C" void kernel_launch(void* const* d_in, const int* in_sizes, int n_in,
                              void* d_out, int out_size) {
    const float* x  = (const float*)d_in[0];       // [N, 128]
    const float* W  = (const float*)d_in[1];       // [128, 128]
    const float* b  = (const float*)d_in[2];       // [128]
    const void*  ei = d_in[3];                     // [2, E] int32 or int64

    int n = in_sizes[0] / IN_C;
    int E = in_sizes[3] / 2;
    float* out = (float*)d_out;

    k_detect<<<1, 256>>>((const int*)ei);
    k_convert<<<(E + 255) / 256, 256>>>(ei, E);
    k_transpose<<<(IN_C * IN_C) / 256, 256>>>(W);
    k_deg_init<<<(n + 255) / 256, 256>>>(n);
    k_deg_count<<<(E + 255) / 256, 256>>>(E);
    k_dinv<<<(n + 255) / 256, 256>>>(n);
    k_gemm<<<(n + GM_ROWS - 1) / GM_ROWS, 256>>>(x, n);
    k_selfinit<<<(n * 32 + 255) / 256, 256>>>(b, out, n);
    k_scatter<<<(E + 7) / 8, 256>>>(out, E);
}

// round 4
// speedup vs baseline: 2.0829x; 2.0829x over previous
#include <cuda_runtime.h>
#include <cuda_bf16.h>

#define IN_C 128
#define MAX_NODES 10000
#define MAX_EDGES 640000

// Scratch (allocation-free rule: __device__ globals)
__device__ float g_Wt[IN_C * IN_C];            // W transposed: Wt[k][o] = W[o][k]
__device__ float g_z[MAX_NODES * IN_C];        // aggregated x (pre-GEMM)
__device__ int   g_cnt[MAX_NODES];             // edge-only in-degree
__device__ float g_dinv[MAX_NODES];            // 1/sqrt(deg) with self loop
__device__ int   g_row[MAX_EDGES];
__device__ int   g_col[MAX_EDGES];
__device__ int   g_ptr[MAX_NODES + 1];         // CSR offsets (by destination)
__device__ int   g_cur[MAX_NODES];             // fill cursors
__device__ int   g_erow[MAX_EDGES];            // CSR source-node list
__device__ int   g_is64;

// ---------------------------------------------------------------------------
// Edge-index dtype detection: int64 data has all-zero odd 32-bit words
// (node ids < 2^31); int32 data essentially never does.
// ---------------------------------------------------------------------------
__global__ void k_detect(const int* __restrict__ ei32) {
    __shared__ int nz;
    if (threadIdx.x == 0) nz = 0;
    __syncthreads();
    if (ei32[2 * threadIdx.x + 1] != 0) atomicAdd(&nz, 1);
    __syncthreads();
    if (threadIdx.x == 0) g_is64 = (nz == 0) ? 1 : 0;
}

// Convert edge index (either dtype) to int32 row/col arrays.
__global__ void k_convert(const void* __restrict__ ei_raw, int E) {
    int e = blockIdx.x * blockDim.x + threadIdx.x;
    if (e >= E) return;
    if (g_is64) {
        const long long* p = (const long long*)ei_raw;
        g_row[e] = (int)p[e];
        g_col[e] = (int)p[(size_t)E + e];
    } else {
        const int* p = (const int*)ei_raw;
        g_row[e] = p[e];
        g_col[e] = p[E + e];
    }
}

// ---------------------------------------------------------------------------
// W transpose: Wt[k*128 + o] = W[o*128 + k]
// ---------------------------------------------------------------------------
__global__ void k_transpose(const float* __restrict__ W) {
    int idx = blockIdx.x * blockDim.x + threadIdx.x;   // 16384 threads
    int o = idx >> 7;
    int k = idx & (IN_C - 1);
    g_Wt[k * IN_C + o] = W[o * IN_C + k];
}

// ---------------------------------------------------------------------------
// Degree pipeline
// ---------------------------------------------------------------------------
__global__ void k_cnt_init(int n) {
    int i = blockIdx.x * blockDim.x + threadIdx.x;
    if (i < n) g_cnt[i] = 0;
}

__global__ void k_deg_count(int E) {
    int e = blockIdx.x * blockDim.x + threadIdx.x;
    if (e < E) atomicAdd(&g_cnt[g_col[e]], 1);
}

__global__ void k_dinv(int n) {
    int i = blockIdx.x * blockDim.x + threadIdx.x;
    if (i < n) g_dinv[i] = rsqrtf((float)(g_cnt[i] + 1));   // +1 self loop
}

// ---------------------------------------------------------------------------
// Exclusive prefix scan of g_cnt -> g_ptr (single block, Hillis-Steele chunks)
// Also initializes g_cur = g_ptr and writes the total to g_ptr[n].
// ---------------------------------------------------------------------------
__global__ void k_scan(int n) {
    __shared__ int sh[1024];
    __shared__ int carry;
    if (threadIdx.x == 0) carry = 0;
    __syncthreads();
    for (int base = 0; base < n; base += 1024) {
        int i = base + threadIdx.x;
        int v = (i < n) ? g_cnt[i] : 0;
        sh[threadIdx.x] = v;
        __syncthreads();
#pragma unroll
        for (int off = 1; off < 1024; off <<= 1) {
            int t = (threadIdx.x >= off) ? sh[threadIdx.x - off] : 0;
            __syncthreads();
            sh[threadIdx.x] += t;
            __syncthreads();
        }
        if (i < n) {
            int excl = carry + sh[threadIdx.x] - v;
            g_ptr[i] = excl;
            g_cur[i] = excl;
        }
        __syncthreads();
        if (threadIdx.x == 0) carry += sh[1023];
        __syncthreads();
    }
    if (threadIdx.x == 0) g_ptr[n] = carry;
}

// ---------------------------------------------------------------------------
// CSR fill: bucket edges by destination (order within bucket irrelevant)
// ---------------------------------------------------------------------------
__global__ void k_fill(int E) {
    int e = blockIdx.x * blockDim.x + threadIdx.x;
    if (e >= E) return;
    int pos = atomicAdd(&g_cur[g_col[e]], 1);
    g_erow[pos] = g_row[e];
}

// ---------------------------------------------------------------------------
// Aggregate (atomic-free): warp per node, lane owns 4 channels.
// z[c] = dinv[c] * ( sum_{e->c} dinv[r]*x[r] + dinv[c]*x[c] )
// ---------------------------------------------------------------------------
__global__ void k_aggregate(const float* __restrict__ x, int n) {
    int node = (blockIdx.x * blockDim.x + threadIdx.x) >> 5;
    if (node >= n) return;
    int lane = threadIdx.x & 31;

    int s = g_ptr[node];
    int e = g_ptr[node + 1];

    float4 acc = make_float4(0.f, 0.f, 0.f, 0.f);

    int i = s;
    for (; i + 4 <= e; i += 4) {
        int r0 = g_erow[i + 0], r1 = g_erow[i + 1];
        int r2 = g_erow[i + 2], r3 = g_erow[i + 3];
        float w0 = g_dinv[r0], w1 = g_dinv[r1];
        float w2 = g_dinv[r2], w3 = g_dinv[r3];
        float4 v0 = *(const float4*)(x + (size_t)r0 * IN_C + lane * 4);
        float4 v1 = *(const float4*)(x + (size_t)r1 * IN_C + lane * 4);
        float4 v2 = *(const float4*)(x + (size_t)r2 * IN_C + lane * 4);
        float4 v3 = *(const float4*)(x + (size_t)r3 * IN_C + lane * 4);
        acc.x += w0 * v0.x + w1 * v1.x + w2 * v2.x + w3 * v3.x;
        acc.y += w0 * v0.y + w1 * v1.y + w2 * v2.y + w3 * v3.y;
        acc.z += w0 * v0.z + w1 * v1.z + w2 * v2.z + w3 * v3.z;
        acc.w += w0 * v0.w + w1 * v1.w + w2 * v2.w + w3 * v3.w;
    }
    for (; i < e; i++) {
        int r = g_erow[i];
        float w = g_dinv[r];
        float4 v = *(const float4*)(x + (size_t)r * IN_C + lane * 4);
        acc.x += w * v.x; acc.y += w * v.y; acc.z += w * v.z; acc.w += w * v.w;
    }

    float dc = g_dinv[node];
    float4 xv = *(const float4*)(x + (size_t)node * IN_C + lane * 4);
    float4 z;
    z.x = dc * (acc.x + dc * xv.x);
    z.y = dc * (acc.y + dc * xv.y);
    z.z = dc * (acc.z + dc * xv.z);
    z.w = dc * (acc.w + dc * xv.w);
    *(float4*)(g_z + (size_t)node * IN_C + lane * 4) = z;
}

// ---------------------------------------------------------------------------
// GEMM + bias: out = z @ W^T + b. Block = 256 threads, 32 rows x 128 cols.
// ---------------------------------------------------------------------------
#define GM_ROWS 32
__global__ void k_gemm_bias(const float* __restrict__ b, float* __restrict__ out, int n) {
    __shared__ float xs[GM_ROWS][IN_C];

    int rowbase = blockIdx.x * GM_ROWS;
    int tid = threadIdx.x;
    int nrows = n - rowbase; if (nrows > GM_ROWS) nrows = GM_ROWS;

    const float4* xg = (const float4*)(g_z + (size_t)rowbase * IN_C);
    float4* xs4 = (float4*)&xs[0][0];
#pragma unroll
    for (int i = 0; i < 4; i++) {
        int idx = tid + i * 256;
        if ((idx >> 5) < nrows) xs4[idx] = xg[idx];
    }
    __syncthreads();

    int warp = tid >> 5, lane = tid & 31;
    int rg = warp >> 2;                       // row group (0..1)
    int o  = ((warp & 3) << 5) + lane;        // output column (0..127)

    float acc[16];
#pragma unroll
    for (int r = 0; r < 16; r++) acc[r] = 0.0f;

    const float* xbase = &xs[rg * 16][0];

#pragma unroll 4
    for (int k = 0; k < IN_C; k++) {
        float w = __ldg(&g_Wt[k * IN_C + o]);
#pragma unroll
        for (int r = 0; r < 16; r++)
            acc[r] += xbase[r * IN_C + k] * w;
    }

    float bo = __ldg(&b[o]);
    int rmax = nrows - rg * 16;
#pragma unroll
    for (int r = 0; r < 16; r++) {
        if (r < rmax)
            out[(size_t)(rowbase + rg * 16 + r) * IN_C + o] = acc[r] + bo;
    }
}

// ---------------------------------------------------------------------------
extern "C" void kernel_launch(void* const* d_in, const int* in_sizes, int n_in,
                              void* d_out, int out_size) {
    const float* x  = (const float*)d_in[0];       // [N, 128]
    const float* W  = (const float*)d_in[1];       // [128, 128]
    const float* b  = (const float*)d_in[2];       // [128]
    const void*  ei = d_in[3];                     // [2, E] int32 or int64

    int n = in_sizes[0] / IN_C;
    int E = in_sizes[3] / 2;
    float* out = (float*)d_out;

    k_detect<<<1, 256>>>((const int*)ei);
    k_convert<<<(E + 255) / 256, 256>>>(ei, E);
    k_transpose<<<(IN_C * IN_C) / 256, 256>>>(W);
    k_cnt_init<<<(n + 255) / 256, 256>>>(n);
    k_deg_count<<<(E + 255) / 256, 256>>>(E);
    k_dinv<<<(n + 255) / 256, 256>>>(n);
    k_scan<<<1, 1024>>>(n);
    k_fill<<<(E + 255) / 256, 256>>>(E);
    k_aggregate<<<(n + 7) / 8, 256>>>(x, n);
    k_gemm_bias<<<(n + GM_ROWS - 1) / GM_ROWS, 256>>>(b, out, n);
}

// round 5
// speedup vs baseline: 2.4344x; 1.1688x over previous
#include <cuda_runtime.h>
#include <cuda_fp16.h>

#define IN_C 128
#define MAX_NODES 10000
#define MAX_EDGES 640000

// Scratch (allocation-free rule: __device__ globals)
__device__ float  g_Wt[IN_C * IN_C];            // W transposed
__device__ float  g_z[MAX_NODES * IN_C];        // aggregated x (pre-GEMM)
__device__ __half g_xh[MAX_NODES * IN_C];       // fp16 copy of x for gather
__device__ int    g_cnt[MAX_NODES];             // edge-only in-degree
__device__ float  g_dinv[MAX_NODES];            // 1/sqrt(deg+1)
__device__ int    g_ptr[MAX_NODES + 1];         // CSR offsets (by destination)
__device__ int    g_cur[MAX_NODES];             // fill cursors
__device__ int    g_erow[MAX_EDGES];            // CSR source-node list
__device__ int    g_is64;

// ---------------------------------------------------------------------------
// Fused prologue: dtype detect (block 0) + zero cnt + transpose W + x -> fp16
// ---------------------------------------------------------------------------
__global__ void k_pre(const int* __restrict__ ei32, const float* __restrict__ x,
                      const float* __restrict__ W, int n) {
    // dtype detect: int64 data has all-zero odd 32-bit words
    if (blockIdx.x == 0) {
        __shared__ int nz;
        if (threadIdx.x == 0) nz = 0;
        __syncthreads();
        if (threadIdx.x < 256 && ei32[2 * threadIdx.x + 1] != 0) atomicAdd(&nz, 1);
        __syncthreads();
        if (threadIdx.x == 0) g_is64 = (nz == 0) ? 1 : 0;
    }

    int tid = blockIdx.x * blockDim.x + threadIdx.x;
    int nth = gridDim.x * blockDim.x;

    for (int i = tid; i < n; i += nth) g_cnt[i] = 0;

    for (int idx = tid; idx < IN_C * IN_C; idx += nth) {
        int o = idx >> 7, k = idx & (IN_C - 1);
        g_Wt[k * IN_C + o] = W[o * IN_C + k];
    }

    // x -> fp16 (vector: float4 in, 4 halves out)
    int n4 = n * (IN_C / 4);
    for (int idx = tid; idx < n4; idx += nth) {
        float4 v = ((const float4*)x)[idx];
        __half2 lo = __floats2half2_rn(v.x, v.y);
        __half2 hi = __floats2half2_rn(v.z, v.w);
        ((__half2*)g_xh)[idx * 2]     = lo;
        ((__half2*)g_xh)[idx * 2 + 1] = hi;
    }
}

// ---------------------------------------------------------------------------
// Convert edge index to nothing stored for row (fill reads again) — we fold
// the count here: one pass computes in-degree while indices are hot.
// ---------------------------------------------------------------------------
__global__ void k_count(const void* __restrict__ ei_raw, int E) {
    int e = blockIdx.x * blockDim.x + threadIdx.x;
    if (e >= E) return;
    int col;
    if (g_is64) col = (int)((const long long*)ei_raw)[(size_t)E + e];
    else        col = ((const int*)ei_raw)[E + e];
    atomicAdd(&g_cnt[col], 1);
}

// ---------------------------------------------------------------------------
// Warp-shuffle exclusive scan of g_cnt -> g_ptr, plus dinv and cursors.
// Single block of 1024, 10 chunks for n=10000.
// ---------------------------------------------------------------------------
__global__ void k_scan_dinv(int n) {
    __shared__ int warpsum[32];
    __shared__ int carry_s;
    int tid = threadIdx.x, lane = tid & 31, wid = tid >> 5;
    if (tid == 0) carry_s = 0;
    __syncthreads();

    for (int base = 0; base < n; base += 1024) {
        int i = base + tid;
        int v = (i < n) ? g_cnt[i] : 0;

        int incl = v;
#pragma unroll
        for (int off = 1; off < 32; off <<= 1) {
            int t = __shfl_up_sync(0xffffffff, incl, off);
            if (lane >= off) incl += t;
        }
        if (lane == 31) warpsum[wid] = incl;
        __syncthreads();
        if (wid == 0) {
            int s = warpsum[lane];
#pragma unroll
            for (int off = 1; off < 32; off <<= 1) {
                int t = __shfl_up_sync(0xffffffff, s, off);
                if (lane >= off) s += t;
            }
            warpsum[lane] = s;
        }
        __syncthreads();

        int warpbase = (wid > 0) ? warpsum[wid - 1] : 0;
        int excl = carry_s + warpbase + incl - v;
        if (i < n) {
            g_ptr[i]  = excl;
            g_cur[i]  = excl;
            g_dinv[i] = rsqrtf((float)(v + 1));    // +1 self loop
        }
        __syncthreads();
        if (tid == 0) carry_s += warpsum[31];
        __syncthreads();
    }
    if (tid == 0) g_ptr[n] = carry_s;
}

// ---------------------------------------------------------------------------
// CSR fill: bucket source nodes by destination
// ---------------------------------------------------------------------------
__global__ void k_fill(const void* __restrict__ ei_raw, int E) {
    int e = blockIdx.x * blockDim.x + threadIdx.x;
    if (e >= E) return;
    int row, col;
    if (g_is64) {
        const long long* p = (const long long*)ei_raw;
        row = (int)p[e];
        col = (int)p[(size_t)E + e];
    } else {
        const int* p = (const int*)ei_raw;
        row = p[e];
        col = p[E + e];
    }
    int pos = atomicAdd(&g_cur[col], 1);
    g_erow[pos] = row;
}

// ---------------------------------------------------------------------------
// Aggregate (atomic-free): warp per node, lane owns 4 channels.
// Gathers from fp16 x copy (halves L2 traffic), accumulates fp32.
// z[c] = dinv[c] * ( sum_{e->c} dinv[r]*xh[r] + dinv[c]*x[c] )
// ---------------------------------------------------------------------------
__global__ void k_aggregate(const float* __restrict__ x, int n) {
    int node = (blockIdx.x * blockDim.x + threadIdx.x) >> 5;
    if (node >= n) return;
    int lane = threadIdx.x & 31;

    int s = g_ptr[node];
    int e = g_ptr[node + 1];

    float4 acc = make_float4(0.f, 0.f, 0.f, 0.f);

    int i = s;
    for (; i + 4 <= e; i += 4) {
        int r0 = g_erow[i + 0], r1 = g_erow[i + 1];
        int r2 = g_erow[i + 2], r3 = g_erow[i + 3];
        float w0 = g_dinv[r0], w1 = g_dinv[r1];
        float w2 = g_dinv[r2], w3 = g_dinv[r3];
        __half2 a0 = *(const __half2*)(g_xh + (size_t)r0 * IN_C + lane * 4);
        __half2 b0 = *(const __half2*)(g_xh + (size_t)r0 * IN_C + lane * 4 + 2);
        __half2 a1 = *(const __half2*)(g_xh + (size_t)r1 * IN_C + lane * 4);
        __half2 b1 = *(const __half2*)(g_xh + (size_t)r1 * IN_C + lane * 4 + 2);
        __half2 a2 = *(const __half2*)(g_xh + (size_t)r2 * IN_C + lane * 4);
        __half2 b2 = *(const __half2*)(g_xh + (size_t)r2 * IN_C + lane * 4 + 2);
        __half2 a3 = *(const __half2*)(g_xh + (size_t)r3 * IN_C + lane * 4);
        __half2 b3 = *(const __half2*)(g_xh + (size_t)r3 * IN_C + lane * 4 + 2);
        float2 f;
        f = __half22float2(a0); acc.x += w0 * f.x; acc.y += w0 * f.y;
        f = __half22float2(b0); acc.z += w0 * f.x; acc.w += w0 * f.y;
        f = __half22float2(a1); acc.x += w1 * f.x; acc.y += w1 * f.y;
        f = __half22float2(b1); acc.z += w1 * f.x; acc.w += w1 * f.y;
        f = __half22float2(a2); acc.x += w2 * f.x; acc.y += w2 * f.y;
        f = __half22float2(b2); acc.z += w2 * f.x; acc.w += w2 * f.y;
        f = __half22float2(a3); acc.x += w3 * f.x; acc.y += w3 * f.y;
        f = __half22float2(b3); acc.z += w3 * f.x; acc.w += w3 * f.y;
    }
    for (; i < e; i++) {
        int r = g_erow[i];
        float w = g_dinv[r];
        __half2 a = *(const __half2*)(g_xh + (size_t)r * IN_C + lane * 4);
        __half2 b = *(const __half2*)(g_xh + (size_t)r * IN_C + lane * 4 + 2);
        float2 f;
        f = __half22float2(a); acc.x += w * f.x; acc.y += w * f.y;
        f = __half22float2(b); acc.z += w * f.x; acc.w += w * f.y;
    }

    float dc = g_dinv[node];
    float4 xv = *(const float4*)(x + (size_t)node * IN_C + lane * 4);  // self term fp32
    float4 z;
    z.x = dc * (acc.x + dc * xv.x);
    z.y = dc * (acc.y + dc * xv.y);
    z.z = dc * (acc.z + dc * xv.z);
    z.w = dc * (acc.w + dc * xv.w);
    *(float4*)(g_z + (size_t)node * IN_C + lane * 4) = z;
}

// ---------------------------------------------------------------------------
// GEMM + bias: out = z @ W^T + b. Block = 256 threads, 32 rows x 128 cols.
// ---------------------------------------------------------------------------
#define GM_ROWS 32
__global__ void k_gemm_bias(const float* __restrict__ b, float* __restrict__ out, int n) {
    __shared__ float xs[GM_ROWS][IN_C];

    int rowbase = blockIdx.x * GM_ROWS;
    int tid = threadIdx.x;
    int nrows = n - rowbase; if (nrows > GM_ROWS) nrows = GM_ROWS;

    const float4* xg = (const float4*)(g_z + (size_t)rowbase * IN_C);
    float4* xs4 = (float4*)&xs[0][0];
#pragma unroll
    for (int i = 0; i < 4; i++) {
        int idx = tid + i * 256;
        if ((idx >> 5) < nrows) xs4[idx] = xg[idx];
    }
    __syncthreads();

    int warp = tid >> 5, lane = tid & 31;
    int rg = warp >> 2;
    int o  = ((warp & 3) << 5) + lane;

    float acc[16];
#pragma unroll
    for (int r = 0; r < 16; r++) acc[r] = 0.0f;

    const float* xbase = &xs[rg * 16][0];

#pragma unroll 4
    for (int k = 0; k < IN_C; k++) {
        float w = __ldg(&g_Wt[k * IN_C + o]);
#pragma unroll
        for (int r = 0; r < 16; r++)
            acc[r] += xbase[r * IN_C + k] * w;
    }

    float bo = __ldg(&b[o]);
    int rmax = nrows - rg * 16;
#pragma unroll
    for (int r = 0; r < 16; r++) {
        if (r < rmax)
            out[(size_t)(rowbase + rg * 16 + r) * IN_C + o] = acc[r] + bo;
    }
}

// ---------------------------------------------------------------------------
extern "C" void kernel_launch(void* const* d_in, const int* in_sizes, int n_in,
                              void* d_out, int out_size) {
    const float* x  = (const float*)d_in[0];       // [N, 128]
    const float* W  = (const float*)d_in[1];       // [128, 128]
    const float* b  = (const float*)d_in[2];       // [128]
    const void*  ei = d_in[3];                     // [2, E] int32 or int64

    int n = in_sizes[0] / IN_C;
    int E = in_sizes[3] / 2;
    float* out = (float*)d_out;

    k_pre<<<80, 256>>>((const int*)ei, x, W, n);
    k_count<<<(E + 255) / 256, 256>>>(ei, E);
    k_scan_dinv<<<1, 1024>>>(n);
    k_fill<<<(E + 255) / 256, 256>>>(ei, E);
    k_aggregate<<<(n + 7) / 8, 256>>>(x, n);
    k_gemm_bias<<<(n + GM_ROWS - 1) / GM_ROWS, 256>>>(b, out, n);
}